// round 17
// baseline (speedup 1.0000x reference)
#include <cuda_runtime.h>
#include <cuda_fp16.h>
#include <cstdint>

// EdgeNetwork R16 — fp16 mma.sync, M=32 per warp: two m16 tiles share every
// B fragment -> B-LDS bytes per edge halved (L1 is bytes-bound; B was 73% of
// smem traffic). 8 warps x 32 edges = 256-edge CTA tile, 2 CTAs/SM.

#define XSW 76    // X row stride (words); banks 12qr+qc+{0} distinct mod 32
#define WQS 66    // W pair-row stride; LDS.64 frags conflict-free
#define TPB 2     // 256-edge tiles per CTA

#define X_OFF   0
#define W1_OFF  (256 * XSW)                  // 19456
#define W2_OFF  (W1_OFF + 72 * WQS)          // 24208
#define PRM_OFF (W2_OFF + 32 * WQS)          // 26320
#define SMEM_WORDS (PRM_OFF + 452)           // 26772
#define SMEM_BYTES (SMEM_WORDS * 4)          // 107088

__device__ __forceinline__ uint32_t h2pack(float lo, float hi) {
    __half2 h = __floats2half2_rn(lo, hi);
    return *(uint32_t*)&h;
}

#define MMA_F16(d, a, b0, b1) \
    asm volatile("mma.sync.aligned.m16n8k16.row.col.f32.f16.f16.f32 " \
        "{%0,%1,%2,%3}, {%4,%5,%6,%7}, {%8,%9}, {%0,%1,%2,%3};" \
        : "+f"((d)[0]), "+f"((d)[1]), "+f"((d)[2]), "+f"((d)[3]) \
        : "r"((a)[0]), "r"((a)[1]), "r"((a)[2]), "r"((a)[3]), "r"(b0), "r"(b1))

__global__ __launch_bounds__(256, 2)
void edgenet_mma(const float* __restrict__ nodef,
                 const int* __restrict__ eidx,
                 const float* __restrict__ eattr,
                 const float* __restrict__ W1, const float* __restrict__ pB1,
                 const float* __restrict__ G1, const float* __restrict__ BE1,
                 const float* __restrict__ W2, const float* __restrict__ pB2,
                 const float* __restrict__ G2, const float* __restrict__ BE2,
                 const float* __restrict__ W3, const float* __restrict__ pB3,
                 float* __restrict__ out, int E, int nNodes)
{
    extern __shared__ uint32_t smem[];
    uint32_t* Xs  = smem + X_OFF;
    uint32_t* W1q = smem + W1_OFF;
    uint32_t* W2q = smem + W2_OFF;
    float*    prm = (float*)(smem + PRM_OFF);

    const int tid  = threadIdx.x;
    const int lane = tid & 31;
    const int wid  = tid >> 5;
    const int qr   = lane >> 2;
    const int qc   = lane & 3;

    // ---- stage weights (k-pair half2, col n -> (n&7)*8+(n>>3)) + params ----
    for (int i = tid; i < 72 * 64; i += 256) {
        int p = i >> 6, n = i & 63;
        W1q[p * WQS + (n & 7) * 8 + (n >> 3)] =
            h2pack(W1[(2 * p) * 64 + n], W1[(2 * p + 1) * 64 + n]);
    }
    for (int i = tid; i < 32 * 64; i += 256) {
        int p = i >> 6, n = i & 63;
        W2q[p * WQS + (n & 7) * 8 + (n >> 3)] =
            h2pack(W2[(2 * p) * 64 + n], W2[(2 * p + 1) * 64 + n]);
    }
    if (tid < 64) {
        prm[tid]       = pB1[tid];
        prm[64 + tid]  = G1[tid];
        prm[128 + tid] = BE1[tid];
        prm[192 + tid] = pB2[tid];
        prm[256 + tid] = G2[tid];
        prm[320 + tid] = BE2[tid];
        prm[384 + tid] = W3[tid];
    }
    if (tid == 0) prm[448] = pB3[0];
    __syncthreads();   // only CTA barrier

    const float4* nf4 = (const float4*)nodef;
    const float4* ea4 = (const float4*)eattr;
    const int rBase = wid * 32;          // warp's 32 rows

    for (int it = 0; it < TPB; ++it) {
        const int eBase = (blockIdx.x * TPB + it) * 256;
        if (eBase >= E) break;

        // ---- warp-local coalesced gather of 32 X rows (fp16) ----
        #pragma unroll
        for (int half = 0; half < 2; ++half) {
            #pragma unroll
            for (int i = 0; i < 16; ++i) {
                int r  = rBase + i * 2 + (lane >> 4);
                int f4 = lane & 15;
                int eg = eBase + r;
                int node = 0;
                if (eg < E) node = half ? eidx[(size_t)E + eg] : eidx[eg];
                if (node < 0) node = 0;
                if (node >= nNodes) node = nNodes - 1;
                float4 v = nf4[(size_t)node * 16 + f4];
                *(uint2*)(Xs + r * XSW + half * 32 + f4 * 2) =
                    make_uint2(h2pack(v.x, v.y), h2pack(v.z, v.w));
            }
        }
        #pragma unroll
        for (int t2 = 0; t2 < 4; ++t2) {
            int idx = t2 * 32 + lane;            // 0..127 over 32 rows x 4 f4
            int r = rBase + (idx >> 2), f4 = idx & 3;
            int eg = eBase + r;
            float4 v = make_float4(0.f, 0.f, 0.f, 0.f);
            if (eg < E) v = ea4[(size_t)eg * 4 + f4];
            *(uint2*)(Xs + r * XSW + 64 + f4 * 2) =
                make_uint2(h2pack(v.x, v.y), h2pack(v.z, v.w));
        }
        __syncwarp();

        // ===== GEMM1: X[32,144] @ W1, B shared across both m16 tiles =====
        float acc[2][8][4];
        #pragma unroll
        for (int mt = 0; mt < 2; ++mt)
            #pragma unroll
            for (int nt = 0; nt < 8; ++nt)
                #pragma unroll
                for (int x = 0; x < 4; ++x) acc[mt][nt][x] = 0.f;

        #pragma unroll 3
        for (int ks = 0; ks < 9; ++ks) {
            int kw = ks * 8;
            uint32_t a[2][4];
            #pragma unroll
            for (int mt = 0; mt < 2; ++mt) {
                const uint32_t* xr = Xs + (rBase + mt * 16 + qr) * XSW + kw + qc;
                a[mt][0] = xr[0];
                a[mt][1] = xr[8 * XSW];
                a[mt][2] = xr[4];
                a[mt][3] = xr[8 * XSW + 4];
            }
            const uint32_t* wbA = W1q + (kw + qc) * WQS + qr * 8;
            const uint32_t* wbB = wbA + 4 * WQS;
            #pragma unroll
            for (int g = 0; g < 4; ++g) {
                uint2 b0 = *(const uint2*)(wbA + 2 * g);
                uint2 b1 = *(const uint2*)(wbB + 2 * g);
                MMA_F16(acc[0][2 * g],     a[0], b0.x, b1.x);
                MMA_F16(acc[0][2 * g + 1], a[0], b0.y, b1.y);
                MMA_F16(acc[1][2 * g],     a[1], b0.x, b1.x);
                MMA_F16(acc[1][2 * g + 1], a[1], b0.y, b1.y);
            }
        }

        // ---- LN1 + leaky, in-register -> GEMM2 A fragments ----
        uint32_t a2[2][4][4];
        #pragma unroll
        for (int mt = 0; mt < 2; ++mt) {
            float s0 = 0.f, ss0 = 0.f, s1 = 0.f, ss1 = 0.f;
            #pragma unroll
            for (int nt = 0; nt < 8; ++nt) {
                int colb = nt * 8 + 2 * qc;
                float v0 = acc[mt][nt][0] + prm[colb];
                float v1 = acc[mt][nt][1] + prm[colb + 1];
                float v2 = acc[mt][nt][2] + prm[colb];
                float v3 = acc[mt][nt][3] + prm[colb + 1];
                acc[mt][nt][0] = v0; acc[mt][nt][1] = v1;
                acc[mt][nt][2] = v2; acc[mt][nt][3] = v3;
                s0 += v0 + v1; ss0 += v0 * v0 + v1 * v1;
                s1 += v2 + v3; ss1 += v2 * v2 + v3 * v3;
            }
            #pragma unroll
            for (int o = 1; o <= 2; o <<= 1) {
                s0  += __shfl_xor_sync(0xffffffffu, s0,  o);
                ss0 += __shfl_xor_sync(0xffffffffu, ss0, o);
                s1  += __shfl_xor_sync(0xffffffffu, s1,  o);
                ss1 += __shfl_xor_sync(0xffffffffu, ss1, o);
            }
            float mu0 = s0 * (1.f / 64.f);
            float rs0 = rsqrtf(ss0 * (1.f / 64.f) - mu0 * mu0 + 1e-5f);
            float mu1 = s1 * (1.f / 64.f);
            float rs1 = rsqrtf(ss1 * (1.f / 64.f) - mu1 * mu1 + 1e-5f);
            #pragma unroll
            for (int nt = 0; nt < 8; ++nt) {
                int colb = nt * 8 + 2 * qc;
                float g0 = prm[64 + colb], g1 = prm[64 + colb + 1];
                float e0 = prm[128 + colb], e1 = prm[128 + colb + 1];
                float y0 = (acc[mt][nt][0] - mu0) * rs0 * g0 + e0;
                float y1 = (acc[mt][nt][1] - mu0) * rs0 * g1 + e1;
                float y2 = (acc[mt][nt][2] - mu1) * rs1 * g0 + e0;
                float y3 = (acc[mt][nt][3] - mu1) * rs1 * g1 + e1;
                y0 = (y0 < 0.f) ? 0.1f * y0 : y0;
                y1 = (y1 < 0.f) ? 0.1f * y1 : y1;
                y2 = (y2 < 0.f) ? 0.1f * y2 : y2;
                y3 = (y3 < 0.f) ? 0.1f * y3 : y3;
                a2[mt][nt >> 1][(nt & 1) * 2]     = h2pack(y0, y1);
                a2[mt][nt >> 1][(nt & 1) * 2 + 1] = h2pack(y2, y3);
            }
        }

        // ===== GEMM2: H[32,64] @ W2, B shared across both m16 tiles =====
        float ac2[2][8][4];
        #pragma unroll
        for (int mt = 0; mt < 2; ++mt)
            #pragma unroll
            for (int nt = 0; nt < 8; ++nt)
                #pragma unroll
                for (int x = 0; x < 4; ++x) ac2[mt][nt][x] = 0.f;

        #pragma unroll
        for (int ks = 0; ks < 4; ++ks) {
            const uint32_t* wbA = W2q + (ks * 8 + qc) * WQS + qr * 8;
            const uint32_t* wbB = wbA + 4 * WQS;
            #pragma unroll
            for (int g = 0; g < 4; ++g) {
                uint2 b0 = *(const uint2*)(wbA + 2 * g);
                uint2 b1 = *(const uint2*)(wbB + 2 * g);
                MMA_F16(ac2[0][2 * g],     a2[0][ks], b0.x, b1.x);
                MMA_F16(ac2[0][2 * g + 1], a2[0][ks], b0.y, b1.y);
                MMA_F16(ac2[1][2 * g],     a2[1][ks], b0.x, b1.x);
                MMA_F16(ac2[1][2 * g + 1], a2[1][ks], b0.y, b1.y);
            }
        }

        // ---- LN2 + leaky + W3 dot + store ----
        #pragma unroll
        for (int mt = 0; mt < 2; ++mt) {
            float s0 = 0.f, ss0 = 0.f, s1 = 0.f, ss1 = 0.f;
            #pragma unroll
            for (int nt = 0; nt < 8; ++nt) {
                int colb = nt * 8 + 2 * qc;
                float v0 = ac2[mt][nt][0] + prm[192 + colb];
                float v1 = ac2[mt][nt][1] + prm[192 + colb + 1];
                float v2 = ac2[mt][nt][2] + prm[192 + colb];
                float v3 = ac2[mt][nt][3] + prm[192 + colb + 1];
                ac2[mt][nt][0] = v0; ac2[mt][nt][1] = v1;
                ac2[mt][nt][2] = v2; ac2[mt][nt][3] = v3;
                s0 += v0 + v1; ss0 += v0 * v0 + v1 * v1;
                s1 += v2 + v3; ss1 += v2 * v2 + v3 * v3;
            }
            #pragma unroll
            for (int o = 1; o <= 2; o <<= 1) {
                s0  += __shfl_xor_sync(0xffffffffu, s0,  o);
                ss0 += __shfl_xor_sync(0xffffffffu, ss0, o);
                s1  += __shfl_xor_sync(0xffffffffu, s1,  o);
                ss1 += __shfl_xor_sync(0xffffffffu, ss1, o);
            }
            float mu0 = s0 * (1.f / 64.f);
            float rs0 = rsqrtf(ss0 * (1.f / 64.f) - mu0 * mu0 + 1e-5f);
            float mu1 = s1 * (1.f / 64.f);
            float rs1 = rsqrtf(ss1 * (1.f / 64.f) - mu1 * mu1 + 1e-5f);

            float p0 = 0.f, p1 = 0.f;
            #pragma unroll
            for (int nt = 0; nt < 8; ++nt) {
                int colb = nt * 8 + 2 * qc;
                float g0 = prm[256 + colb], g1 = prm[256 + colb + 1];
                float e0 = prm[320 + colb], e1 = prm[320 + colb + 1];
                float w0 = prm[384 + colb], w1 = prm[384 + colb + 1];
                float y0 = (ac2[mt][nt][0] - mu0) * rs0 * g0 + e0;
                float y1 = (ac2[mt][nt][1] - mu0) * rs0 * g1 + e1;
                float y2 = (ac2[mt][nt][2] - mu1) * rs1 * g0 + e0;
                float y3 = (ac2[mt][nt][3] - mu1) * rs1 * g1 + e1;
                y0 = (y0 < 0.f) ? 0.1f * y0 : y0;
                y1 = (y1 < 0.f) ? 0.1f * y1 : y1;
                y2 = (y2 < 0.f) ? 0.1f * y2 : y2;
                y3 = (y3 < 0.f) ? 0.1f * y3 : y3;
                p0 += y0 * w0 + y1 * w1;
                p1 += y2 * w0 + y3 * w1;
            }
            #pragma unroll
            for (int o = 1; o <= 2; o <<= 1) {
                p0 += __shfl_xor_sync(0xffffffffu, p0, o);
                p1 += __shfl_xor_sync(0xffffffffu, p1, o);
            }
            if (qc == 0) {
                float b3 = prm[448];
                int e0i = eBase + rBase + mt * 16 + qr;
                int e1i = e0i + 8;
                if (e0i < E) out[e0i] = p0 + b3;
                if (e1i < E) out[e1i] = p1 + b3;
            }
        }
        __syncwarp();   // X rows warp-private; safe to regather next tile
    }
}

extern "C" void kernel_launch(void* const* d_in, const int* in_sizes, int n_in,
                              void* d_out, int out_size)
{
    const float* nodef = (const float*)d_in[0];
    const int*   eidx  = (const int*)d_in[1];   // int32 [2, E]
    const float* eattr = (const float*)d_in[2];
    const float* W1  = (const float*)d_in[3];
    const float* B1  = (const float*)d_in[4];
    const float* G1  = (const float*)d_in[5];
    const float* BE1 = (const float*)d_in[6];
    const float* W2  = (const float*)d_in[7];
    const float* B2  = (const float*)d_in[8];
    const float* G2  = (const float*)d_in[9];
    const float* BE2 = (const float*)d_in[10];
    const float* W3  = (const float*)d_in[11];
    const float* B3  = (const float*)d_in[12];
    float* out = (float*)d_out;

    int E      = out_size;
    int nNodes = in_sizes[0] / 64;
    int nTiles = (E + 255) / 256;
    int grid   = (nTiles + TPB - 1) / TPB;

    cudaFuncSetAttribute(edgenet_mma,
                         cudaFuncAttributeMaxDynamicSharedMemorySize, SMEM_BYTES);
    edgenet_mma<<<grid, 256, SMEM_BYTES>>>(
        nodef, eidx, eattr, W1, B1, G1, BE1, W2, B2, G2, BE2, W3, B3,
        out, E, nNodes);
}